// round 1
// baseline (speedup 1.0000x reference)
#include <cuda_runtime.h>
#include <math.h>

// ---------------- problem constants ----------------
#define Bc    4
#define Tc    2048
#define Cc    1024
#define Hc    64
#define HSc   16
#define NTOK  (Bc*Tc)            // 8192 tokens
#define C4    (Cc/4)             // 256
#define NC    (NTOK*Cc)          // 8,388,608 elements (32MB fp32)
#define DM4   128                // D_MIX*4
#define DDEC  64

// ---------------- scratch (static device memory; no allocation) ----------------
__device__ __align__(16) float g_xx [NC];   // reused as y after mix
__device__ __align__(16) float g_xxx[NC];   // reused as ybar after G1
__device__ __align__(16) float g_h  [NTOK*DM4];
__device__ __align__(16) float g_m0 [NC];   // reused as r
__device__ __align__(16) float g_m1 [NC];   // reused as k
__device__ __align__(16) float g_m2 [NC];   // reused as v
__device__ __align__(16) float g_m3 [NC];   // reused as wexp
__device__ __align__(16) float g_xw [NC];
__device__ __align__(16) float g_xk [NC];
__device__ __align__(16) float g_xv [NC];
__device__ __align__(16) float g_xr [NC];
__device__ __align__(16) float g_t1 [NTOK*DDEC];

// ---------------- elementwise: token shift + maa_x mix ----------------
__global__ void __launch_bounds__(256) k_shift(const float4* __restrict__ x,
                                               const float4* __restrict__ tmx,
                                               float4* __restrict__ oxx,
                                               float4* __restrict__ oxxx)
{
    int i = blockIdx.x * 256 + threadIdx.x;          // over NTOK*C4 exactly
    int c4 = i & (C4 - 1);
    int n  = i >> 8;
    int t  = n & (Tc - 1);
    float4 xv = x[i];
    float4 xp = make_float4(0.f, 0.f, 0.f, 0.f);
    if (t != 0) xp = x[i - C4];
    float4 d;
    d.x = xp.x - xv.x; d.y = xp.y - xv.y; d.z = xp.z - xv.z; d.w = xp.w - xv.w;
    float4 tm = tmx[c4];
    float4 o;
    o.x = fmaf(d.x, tm.x, xv.x); o.y = fmaf(d.y, tm.y, xv.y);
    o.z = fmaf(d.z, tm.z, xv.z); o.w = fmaf(d.w, tm.w, xv.w);
    oxx[i]  = d;
    oxxx[i] = o;
}

// ---------------- elementwise: apply data-dependent mix ----------------
__global__ void __launch_bounds__(256) k_apply(const float4* __restrict__ x,
                                               const float4* __restrict__ xx,
                                               const float4* __restrict__ m0,
                                               const float4* __restrict__ m1,
                                               const float4* __restrict__ m2,
                                               const float4* __restrict__ m3,
                                               const float4* __restrict__ tw,
                                               const float4* __restrict__ tk,
                                               const float4* __restrict__ tv,
                                               const float4* __restrict__ tr,
                                               float4* __restrict__ oxw,
                                               float4* __restrict__ oxk,
                                               float4* __restrict__ oxv,
                                               float4* __restrict__ oxr)
{
    int i  = blockIdx.x * 256 + threadIdx.x;
    int c4 = i & (C4 - 1);
    float4 xv = x[i];
    float4 dx = xx[i];
#define MIX1(OUT, TARR, MARR)                                                   \
    {                                                                           \
        float4 tt = TARR[c4]; float4 mm = MARR[i]; float4 o;                    \
        o.x = fmaf(dx.x, tt.x + mm.x, xv.x);                                    \
        o.y = fmaf(dx.y, tt.y + mm.y, xv.y);                                    \
        o.z = fmaf(dx.z, tt.z + mm.z, xv.z);                                    \
        o.w = fmaf(dx.w, tt.w + mm.w, xv.w);                                    \
        OUT[i] = o;                                                             \
    }
    MIX1(oxw, tw, m0)
    MIX1(oxk, tk, m1)
    MIX1(oxv, tv, m2)
    MIX1(oxr, tr, m3)
#undef MIX1
}

// ---------------- SGEMM (fp32, double-buffered shared) ----------------
// C[N,M] = epi(A[N,K] * B[K,M]); row-major, all tile dims divide shapes exactly.
enum { EPI_NONE = 0, EPI_TANH = 1, EPI_WEXP = 2 };

template<int BN, int BM, int BK, int TN, int TM, int EPI>
__global__ void __launch_bounds__((BN/TN)*(BM/TM))
sgemm(const float* __restrict__ A, const float* __restrict__ Bm,
      float* __restrict__ Cm, int K, int lda, int ldb, int ldc,
      const float* __restrict__ bias)
{
    constexpr int TX = BM / TM;
    constexpr int TY = BN / TN;
    constexpr int NT = TX * TY;
    constexpr int NQ = TN / 4;            // row quadrants (1 or 2)
    constexpr int MQ = TM / 4;            // col quadrants (1 or 2)
    static_assert(BN * BK / 4 == NT, "A tile = 1 float4/thread");
    static_assert(BM * BK / 4 == NT, "B tile = 1 float4/thread");

    const int tid = threadIdx.x;
    const int tx  = tid % TX;
    const int ty  = tid / TX;
    const int rowBase = blockIdx.x * BN;
    const int colBase = blockIdx.y * BM;

    __shared__ float As[2][BK][BN + 4];
    __shared__ float Bs[2][BK][BM];

    constexpr int AKV = BK / 4;
    const int aRow = tid / AKV;
    const int aK   = (tid % AKV) * 4;
    constexpr int BMV = BM / 4;
    const int bK   = tid / BMV;
    const int bCol = (tid % BMV) * 4;

    float acc[TN][TM];
#pragma unroll
    for (int i = 0; i < TN; i++)
#pragma unroll
        for (int j = 0; j < TM; j++) acc[i][j] = 0.f;

    // prologue: tile 0
    float4 aReg = *(const float4*)(A + (size_t)(rowBase + aRow) * lda + aK);
    float4 bReg = *(const float4*)(Bm + (size_t)bK * ldb + colBase + bCol);
    As[0][aK + 0][aRow] = aReg.x;
    As[0][aK + 1][aRow] = aReg.y;
    As[0][aK + 2][aRow] = aReg.z;
    As[0][aK + 3][aRow] = aReg.w;
    *(float4*)&Bs[0][bK][bCol] = bReg;
    __syncthreads();

    const int nT = K / BK;
    int buf = 0;
    for (int t = 0; t < nT; ++t) {
        float4 aN, bN;
        if (t + 1 < nT) {
            int kt = (t + 1) * BK;
            aN = *(const float4*)(A + (size_t)(rowBase + aRow) * lda + kt + aK);
            bN = *(const float4*)(Bm + (size_t)(kt + bK) * ldb + colBase + bCol);
        }
#pragma unroll
        for (int kk = 0; kk < BK; ++kk) {
            float af[TN], bf[TM];
#pragma unroll
            for (int q = 0; q < NQ; q++)
                *(float4*)&af[q * 4] = *(const float4*)&As[buf][kk][q * (BN / NQ) + ty * 4];
#pragma unroll
            for (int p = 0; p < MQ; p++)
                *(float4*)&bf[p * 4] = *(const float4*)&Bs[buf][kk][p * (BM / MQ) + tx * 4];
#pragma unroll
            for (int i = 0; i < TN; i++)
#pragma unroll
                for (int j = 0; j < TM; j++)
                    acc[i][j] = fmaf(af[i], bf[j], acc[i][j]);
        }
        if (t + 1 < nT) {
            buf ^= 1;
            As[buf][aK + 0][aRow] = aN.x;
            As[buf][aK + 1][aRow] = aN.y;
            As[buf][aK + 2][aRow] = aN.z;
            As[buf][aK + 3][aRow] = aN.w;
            *(float4*)&Bs[buf][bK][bCol] = bN;
            __syncthreads();
        }
    }

    // epilogue
#pragma unroll
    for (int q = 0; q < NQ; q++)
#pragma unroll
        for (int e = 0; e < 4; e++) {
            int row = rowBase + q * (BN / NQ) + ty * 4 + e;
#pragma unroll
            for (int p = 0; p < MQ; p++) {
                int col0 = colBase + p * (BM / MQ) + tx * 4;
                float* ap = &acc[q * 4 + e][p * 4];
                float4 o;
                if (EPI == EPI_TANH) {
                    o.x = tanhf(ap[0]); o.y = tanhf(ap[1]);
                    o.z = tanhf(ap[2]); o.w = tanhf(ap[3]);
                } else if (EPI == EPI_WEXP) {
                    float4 bv = *(const float4*)&bias[col0];
                    o.x = expf(-expf(bv.x + ap[0]));
                    o.y = expf(-expf(bv.y + ap[1]));
                    o.z = expf(-expf(bv.z + ap[2]));
                    o.w = expf(-expf(bv.w + ap[3]));
                } else {
                    o.x = ap[0]; o.y = ap[1]; o.z = ap[2]; o.w = ap[3];
                }
                *(float4*)(Cm + (size_t)row * ldc + col0) = o;
            }
        }
}

// ---------------- WKV6 recurrence ----------------
// One warp per (b,h). lane = ih*16 + j: owns S[i][j] for i in [ih*8, ih*8+8).
// r/k/w staged to smem as packed float4 per 64-step chunk; v staged as float.
#define WKV_CT 64
__global__ void __launch_bounds__(32) k_wkv(const float* __restrict__ u_faaaa,
                                            const float* __restrict__ r,
                                            const float* __restrict__ k,
                                            const float* __restrict__ v,
                                            const float* __restrict__ w,
                                            float* __restrict__ y)
{
    const int head_id = blockIdx.x;          // 0..B*H-1
    const int b = head_id >> 6;
    const int h = head_id & 63;
    const int lane = threadIdx.x;
    const int ih = lane >> 4;
    const int j  = lane & 15;
    const int base = (b * Tc) * (Hc * HSc) + h * HSc;   // offset at t=0

    float S[8];
#pragma unroll
    for (int q = 0; q < 8; q++) S[q] = 0.f;
    float u[8];
#pragma unroll
    for (int q = 0; q < 8; q++) u[q] = u_faaaa[h * HSc + ih * 8 + q];

    __shared__ float4 rkw[WKV_CT][HSc];
    __shared__ float  vsh[WKV_CT][HSc];

    for (int t0 = 0; t0 < Tc; t0 += WKV_CT) {
#pragma unroll 4
        for (int idx = lane; idx < WKV_CT * HSc; idx += 32) {
            int tt = idx >> 4;
            int i  = idx & 15;
            int off = base + (t0 + tt) * (Hc * HSc) + i;
            rkw[tt][i] = make_float4(r[off], k[off], w[off], 0.f);
            vsh[tt][i] = v[off];
        }
        __syncwarp();
        for (int tt = 0; tt < WKV_CT; ++tt) {
            float vj  = vsh[tt][j];
            float acc = 0.f;
#pragma unroll
            for (int q = 0; q < 8; q++) {
                float4 e = rkw[tt][ih * 8 + q];
                float kv = e.y * vj;
                acc  = fmaf(e.x, fmaf(u[q], kv, S[q]), acc);
                S[q] = fmaf(e.z, S[q], kv);
            }
            acc += __shfl_xor_sync(0xffffffffu, acc, 16);
            if (ih == 0) y[base + (t0 + tt) * (Hc * HSc) + j] = acc;
        }
        __syncwarp();
    }
}

// ---------------- LayerNorm over C ----------------
__global__ void __launch_bounds__(256) k_ln(const float* __restrict__ y,
                                            const float* __restrict__ g,
                                            const float* __restrict__ bb,
                                            float* __restrict__ out)
{
    const int n   = blockIdx.x;
    const int tid = threadIdx.x;
    const float4* yr = (const float4*)(y + (size_t)n * Cc);
    float4 vv = yr[tid];
    float s = vv.x + vv.y + vv.z + vv.w;
    float q = vv.x * vv.x + vv.y * vv.y + vv.z * vv.z + vv.w * vv.w;
#pragma unroll
    for (int o = 16; o > 0; o >>= 1) {
        s += __shfl_xor_sync(0xffffffffu, s, o);
        q += __shfl_xor_sync(0xffffffffu, q, o);
    }
    __shared__ float ssh[8], qsh[8];
    if ((tid & 31) == 0) { ssh[tid >> 5] = s; qsh[tid >> 5] = q; }
    __syncthreads();
    float st = 0.f, qt = 0.f;
#pragma unroll
    for (int wix = 0; wix < 8; wix++) { st += ssh[wix]; qt += qsh[wix]; }
    float mean = st * (1.0f / Cc);
    float var  = qt * (1.0f / Cc) - mean * mean;
    float rstd = rsqrtf(var + 1e-5f);
    float4 gg = ((const float4*)g)[tid];
    float4 b4 = ((const float4*)bb)[tid];
    float4 o;
    o.x = (vv.x - mean) * rstd * gg.x + b4.x;
    o.y = (vv.y - mean) * rstd * gg.y + b4.y;
    o.z = (vv.z - mean) * rstd * gg.z + b4.z;
    o.w = (vv.w - mean) * rstd * gg.w + b4.w;
    ((float4*)(out + (size_t)n * Cc))[tid] = o;
}

// ---------------- launcher ----------------
extern "C" void kernel_launch(void* const* d_in, const int* in_sizes, int n_in,
                              void* d_out, int out_size)
{
    (void)in_sizes; (void)n_in; (void)out_size;
    const float* x     = (const float*)d_in[0];
    const float* tmx   = (const float*)d_in[1];
    const float* tmw   = (const float*)d_in[2];
    const float* tmk   = (const float*)d_in[3];
    const float* tmv   = (const float*)d_in[4];
    const float* tmr   = (const float*)d_in[5];
    const float* w1    = (const float*)d_in[6];   // [C,128]
    const float* w2    = (const float*)d_in[7];   // [4,32,C]
    const float* tdec  = (const float*)d_in[8];   // [C]
    const float* dw1   = (const float*)d_in[9];   // [C,64]
    const float* dw2   = (const float*)d_in[10];  // [64,C]
    const float* faaaa = (const float*)d_in[11];  // [H,HS]
    const float* Wr    = (const float*)d_in[12];
    const float* Wk    = (const float*)d_in[13];
    const float* Wv    = (const float*)d_in[14];
    const float* Wo    = (const float*)d_in[15];
    const float* lng   = (const float*)d_in[16];
    const float* lnb   = (const float*)d_in[17];
    float* out = (float*)d_out;

    static float *p_xx = nullptr, *p_xxx, *p_h, *p_m0, *p_m1, *p_m2, *p_m3,
                 *p_xw, *p_xk, *p_xv, *p_xr, *p_t1;
    if (!p_xx) {
        cudaGetSymbolAddress((void**)&p_xx,  g_xx);
        cudaGetSymbolAddress((void**)&p_xxx, g_xxx);
        cudaGetSymbolAddress((void**)&p_h,   g_h);
        cudaGetSymbolAddress((void**)&p_m0,  g_m0);
        cudaGetSymbolAddress((void**)&p_m1,  g_m1);
        cudaGetSymbolAddress((void**)&p_m2,  g_m2);
        cudaGetSymbolAddress((void**)&p_m3,  g_m3);
        cudaGetSymbolAddress((void**)&p_xw,  g_xw);
        cudaGetSymbolAddress((void**)&p_xk,  g_xk);
        cudaGetSymbolAddress((void**)&p_xv,  g_xv);
        cudaGetSymbolAddress((void**)&p_xr,  g_xr);
        cudaGetSymbolAddress((void**)&p_t1,  g_t1);
    }
    // buffer reuse aliases
    float* p_r  = p_m0;   // r overwrites m0 (dead after k_apply)
    float* p_k  = p_m1;
    float* p_v  = p_m2;
    float* p_we = p_m3;   // exp(-exp(w))
    float* p_y  = p_xx;   // y overwrites xx (dead after k_apply)
    float* p_yn = p_xxx;  // ln(y) overwrites xxx (dead after G1)

    // 1) token shift + maa_x mix
    k_shift<<<NTOK, 256>>>((const float4*)x, (const float4*)tmx,
                           (float4*)p_xx, (float4*)p_xxx);

    // 2) h = tanh(xxx @ W1)   [8192,1024]x[1024,128]
    sgemm<64, 64, 16, 4, 4, EPI_TANH><<<dim3(NTOK / 64, DM4 / 64), 256>>>(
        p_xxx, w1, p_h, Cc, Cc, DM4, DM4, nullptr);

    // 3) m_f = h[:,f*32:..] @ W2[f]   4x ([8192,32]x[32,1024])
    float* pm[4] = { p_m0, p_m1, p_m2, p_m3 };
    for (int f = 0; f < 4; ++f)
        sgemm<64, 64, 16, 4, 4, EPI_NONE><<<dim3(NTOK / 64, Cc / 64), 256>>>(
            p_h + f * 32, w2 + f * 32 * Cc, pm[f], 32, DM4, Cc, Cc, nullptr);

    // 4) xw/xk/xv/xr = x + xx*(time_maa_* + m_*)
    k_apply<<<NTOK, 256>>>((const float4*)x, (const float4*)p_xx,
                           (const float4*)p_m0, (const float4*)p_m1,
                           (const float4*)p_m2, (const float4*)p_m3,
                           (const float4*)tmw, (const float4*)tmk,
                           (const float4*)tmv, (const float4*)tmr,
                           (float4*)p_xw, (float4*)p_xk,
                           (float4*)p_xv, (float4*)p_xr);

    // 5) t1 = tanh(xw @ decay_w1)  [8192,1024]x[1024,64]
    sgemm<64, 64, 16, 4, 4, EPI_TANH><<<dim3(NTOK / 64, 1), 256>>>(
        p_xw, dw1, p_t1, Cc, Cc, DDEC, DDEC, nullptr);

    // 6) wexp = exp(-exp(time_decay + t1 @ decay_w2))  [8192,64]x[64,1024]
    sgemm<128, 128, 8, 8, 8, EPI_WEXP><<<dim3(NTOK / 128, Cc / 128), 256>>>(
        p_t1, dw2, p_we, DDEC, DDEC, Cc, Cc, tdec);

    // 7) r/k/v projections  [8192,1024]x[1024,1024]
    sgemm<128, 128, 8, 8, 8, EPI_NONE><<<dim3(NTOK / 128, Cc / 128), 256>>>(
        p_xr, Wr, p_r, Cc, Cc, Cc, Cc, nullptr);
    sgemm<128, 128, 8, 8, 8, EPI_NONE><<<dim3(NTOK / 128, Cc / 128), 256>>>(
        p_xk, Wk, p_k, Cc, Cc, Cc, Cc, nullptr);
    sgemm<128, 128, 8, 8, 8, EPI_NONE><<<dim3(NTOK / 128, Cc / 128), 256>>>(
        p_xv, Wv, p_v, Cc, Cc, Cc, Cc, nullptr);

    // 8) WKV6 recurrence
    k_wkv<<<Bc * Hc, 32>>>(faaaa, p_r, p_k, p_v, p_we, p_y);

    // 9) LayerNorm
    k_ln<<<NTOK, 256>>>(p_y, lng, lnb, p_yn);

    // 10) out = ybar @ W_o
    sgemm<128, 128, 8, 8, 8, EPI_NONE><<<dim3(NTOK / 128, Cc / 128), 256>>>(
        p_yn, Wo, out, Cc, Cc, Cc, Cc, nullptr);
}

// round 3
// speedup vs baseline: 1.7691x; 1.7691x over previous
#include <cuda_runtime.h>
#include <cuda_bf16.h>
#include <math.h>
#include <cstdint>

// ---------------- problem constants ----------------
#define Bc    4
#define Tc    2048
#define Cc    1024
#define Hc    64
#define HSc   16
#define NTOK  (Bc*Tc)            // 8192 tokens
#define C4    (Cc/4)             // 256
#define NC    (NTOK*Cc)          // 8,388,608 fp32 (32MB)
#define DM4   128
#define DDEC  64

// ---------------- scratch (static device memory) ----------------
__device__ __align__(16) float g_xx [NC];
__device__ __align__(16) float g_xxx[NC];   // reused as y, then ybar
__device__ __align__(16) float g_h  [NTOK*DM4];
__device__ __align__(16) float g_r  [NC];
__device__ __align__(16) float g_k  [NC];
__device__ __align__(16) float g_v  [NC];
__device__ __align__(16) float g_we [NC];
__device__ __align__(16) float g_xw [NC];
__device__ __align__(16) float g_xk [NC];
__device__ __align__(16) float g_xv [NC];
__device__ __align__(16) float g_xr [NC];
__device__ __align__(16) float g_t1 [NTOK*DDEC];

// ---------------- warp-mma helpers ----------------
__device__ __forceinline__ uint32_t smem_u32(const void* p) {
    uint32_t a;
    asm("{ .reg .u64 t; cvta.to.shared.u64 t, %1; cvt.u32.u64 %0, t; }" : "=r"(a) : "l"(p));
    return a;
}
__device__ __forceinline__ void ldsm4(uint32_t* r, uint32_t addr) {
    asm volatile("ldmatrix.sync.aligned.m8n8.x4.shared.b16 {%0,%1,%2,%3}, [%4];"
        : "=r"(r[0]), "=r"(r[1]), "=r"(r[2]), "=r"(r[3]) : "r"(addr));
}
__device__ __forceinline__ void ldsm4t(uint32_t* r, uint32_t addr) {
    asm volatile("ldmatrix.sync.aligned.m8n8.x4.trans.shared.b16 {%0,%1,%2,%3}, [%4];"
        : "=r"(r[0]), "=r"(r[1]), "=r"(r[2]), "=r"(r[3]) : "r"(addr));
}
__device__ __forceinline__ void mma16816(float* d, const uint32_t* a, const uint32_t* b) {
    asm volatile(
        "mma.sync.aligned.m16n8k16.row.col.f32.bf16.bf16.f32 "
        "{%0,%1,%2,%3}, {%4,%5,%6,%7}, {%8,%9}, {%0,%1,%2,%3};"
        : "+f"(d[0]), "+f"(d[1]), "+f"(d[2]), "+f"(d[3])
        : "r"(a[0]), "r"(a[1]), "r"(a[2]), "r"(a[3]), "r"(b[0]), "r"(b[1]));
}
__device__ __forceinline__ uint32_t pack_bf(__nv_bfloat16 a, __nv_bfloat16 b) {
    __nv_bfloat162 t = __halves2bfloat162(a, b);
    return *reinterpret_cast<uint32_t*>(&t);
}
__device__ __forceinline__ void cvt_hilo(float4 v, uint2& hi, uint2& lo) {
    __nv_bfloat16 hx = __float2bfloat16_rn(v.x);
    __nv_bfloat16 hy = __float2bfloat16_rn(v.y);
    __nv_bfloat16 hz = __float2bfloat16_rn(v.z);
    __nv_bfloat16 hw = __float2bfloat16_rn(v.w);
    hi.x = pack_bf(hx, hy); hi.y = pack_bf(hz, hw);
    lo.x = pack_bf(__float2bfloat16_rn(v.x - __bfloat162float(hx)),
                   __float2bfloat16_rn(v.y - __bfloat162float(hy)));
    lo.y = pack_bf(__float2bfloat16_rn(v.z - __bfloat162float(hz)),
                   __float2bfloat16_rn(v.w - __bfloat162float(hw)));
}

// ---------------- tensor-core GEMM via mma.sync (bf16x3 split) ----------------
// C[M, N] = epi(A[M,K] @ B[K,N]); A row-major, B row-major [K,N].
// M tile 128, N tile BN, K tile 16 fp32 (hi/lo bf16 split, 3 cross products).
enum { EPI_NONE = 0, EPI_TANH = 1, EPI_WEXP = 2, EPI_MIX = 3 };

template<int BN, int EPI>
__global__ void __launch_bounds__(256, 2)
mgemm(const float* __restrict__ A, const float* __restrict__ Bg,
      float* __restrict__ Cm, int K, int lda, int ldb, int ldc,
      const float* __restrict__ bias,
      const float* __restrict__ px, const float* __restrict__ pxx)
{
    constexpr int BK  = 16;
    constexpr int AST = 40;            // uint16 stride per A row (16 hi | 16 lo | 8 pad)
    constexpr int BST = BN * 2 + 8;    // uint16 stride per B row (BN hi | BN lo | 8 pad)
    constexpr int NF  = BN / 32;       // n-frags (8 wide) per warp
    constexpr int NF2 = NF / 2;        // ldmatrix.x4.trans loads 2 n-frags
    constexpr int A_F4 = 2;            // 128*16/4 / 256
    constexpr int B_F4 = (BK * BN / 4) / 256;  // BN=128: 2, BN=64: 1

    __shared__ uint16_t As[2][128 * AST];
    __shared__ uint16_t Bs[2][BK * BST];

    const int tid  = threadIdx.x;
    const int wid  = tid >> 5;
    const int lane = tid & 31;
    const int warpM = (wid >> 2) * 64;
    const int warpN = (wid & 3) * (BN / 4);

    const int rowBase = blockIdx.x * 128;
    const int colBase = blockIdx.y * BN;

    float acc[4][NF][4];
#pragma unroll
    for (int i = 0; i < 4; i++)
#pragma unroll
        for (int j = 0; j < NF; j++)
#pragma unroll
            for (int e = 0; e < 4; e++) acc[i][j][e] = 0.f;

    // per-lane ldmatrix base addressing
    const uint32_t aBase = smem_u32(As);
    const uint32_t bBase = smem_u32(Bs);
    const int lrow = lane & 15;
    const int lhalf = (lane >> 4) * 8;
    // A: addr(mi, sel) = aBase + buf*... + (warpM + mi*16 + lrow)*80 + (sel*16 + lhalf)*2
    const uint32_t aLane = (uint32_t)((warpM + lrow) * AST + lhalf) * 2;
    // B: addr(nf2, sel) = bBase + buf*... + lrow*BST*2 + (sel*BN + warpN + nf2*16 + lhalf)*2
    const uint32_t bLane = (uint32_t)(lrow * BST + warpN + lhalf) * 2;

    // global load index precompute
    const int aRowL = (tid * A_F4) >> 2;          // but loads strided; compute per i below
    (void)aRowL;

    const int nT = K / BK;
    float4 avs[A_F4], bvs[B_F4];

    // ---- prologue: load tile 0 into regs ----
#pragma unroll
    for (int i = 0; i < A_F4; i++) {
        int idx = i * 256 + tid;           // 512 float4 slots
        int r = idx >> 2, q = idx & 3;
        avs[i] = *(const float4*)(A + (size_t)(rowBase + r) * lda + q * 4);
    }
#pragma unroll
    for (int i = 0; i < B_F4; i++) {
        int idx = i * 256 + tid;
        int r, q;
        if (BN == 128) { r = idx >> 5; q = idx & 31; }
        else           { r = idx >> 4; q = idx & 15; }
        bvs[i] = *(const float4*)(Bg + (size_t)r * ldb + colBase + q * 4);
    }
    // store tile 0
#pragma unroll
    for (int i = 0; i < A_F4; i++) {
        int idx = i * 256 + tid;
        int r = idx >> 2, q = idx & 3;
        uint2 hi, lo; cvt_hilo(avs[i], hi, lo);
        *(uint2*)&As[0][r * AST + q * 4]      = hi;
        *(uint2*)&As[0][r * AST + 16 + q * 4] = lo;
    }
#pragma unroll
    for (int i = 0; i < B_F4; i++) {
        int idx = i * 256 + tid;
        int r, q;
        if (BN == 128) { r = idx >> 5; q = idx & 31; }
        else           { r = idx >> 4; q = idx & 15; }
        uint2 hi, lo; cvt_hilo(bvs[i], hi, lo);
        *(uint2*)&Bs[0][r * BST + q * 4]      = hi;
        *(uint2*)&Bs[0][r * BST + BN + q * 4] = lo;
    }
    __syncthreads();

    for (int t = 0; ; ) {
        const int buf = t & 1;
        // issue global loads for next tile
        if (t + 1 < nT) {
            int k0 = (t + 1) * BK;
#pragma unroll
            for (int i = 0; i < A_F4; i++) {
                int idx = i * 256 + tid;
                int r = idx >> 2, q = idx & 3;
                avs[i] = *(const float4*)(A + (size_t)(rowBase + r) * lda + k0 + q * 4);
            }
#pragma unroll
            for (int i = 0; i < B_F4; i++) {
                int idx = i * 256 + tid;
                int r, q;
                if (BN == 128) { r = idx >> 5; q = idx & 31; }
                else           { r = idx >> 4; q = idx & 15; }
                bvs[i] = *(const float4*)(Bg + (size_t)(k0 + r) * ldb + colBase + q * 4);
            }
        }

        // ---- compute from smem buf ----
        {
            const uint32_t ab = aBase + (uint32_t)buf * (128 * AST * 2);
            const uint32_t bb = bBase + (uint32_t)buf * (BK * BST * 2);
            uint32_t af[4][4];
            uint32_t bh[NF][2], bl[NF][2];
#pragma unroll
            for (int mi = 0; mi < 4; mi++)
                ldsm4(af[mi], ab + aLane + (uint32_t)(mi * 16 * AST) * 2);
#pragma unroll
            for (int p = 0; p < NF2; p++)
                ldsm4t(&bh[p * 2][0], bb + bLane + (uint32_t)(p * 16) * 2);
#pragma unroll
            for (int p = 0; p < NF2; p++)
                ldsm4t(&bl[p * 2][0], bb + bLane + (uint32_t)(BN + p * 16) * 2);
            // hi*hi
#pragma unroll
            for (int mi = 0; mi < 4; mi++)
#pragma unroll
                for (int ni = 0; ni < NF; ni++)
                    mma16816(acc[mi][ni], af[mi], bh[ni]);
            // hi*lo
#pragma unroll
            for (int mi = 0; mi < 4; mi++)
#pragma unroll
                for (int ni = 0; ni < NF; ni++)
                    mma16816(acc[mi][ni], af[mi], bl[ni]);
            // lo*hi
#pragma unroll
            for (int mi = 0; mi < 4; mi++)
                ldsm4(af[mi], ab + aLane + (uint32_t)(mi * 16 * AST + 16) * 2);
#pragma unroll
            for (int mi = 0; mi < 4; mi++)
#pragma unroll
                for (int ni = 0; ni < NF; ni++)
                    mma16816(acc[mi][ni], af[mi], bh[ni]);
        }

        if (++t == nT) break;

        // store next tile to other buffer
        const int nb = t & 1;
#pragma unroll
        for (int i = 0; i < A_F4; i++) {
            int idx = i * 256 + tid;
            int r = idx >> 2, q = idx & 3;
            uint2 hi, lo; cvt_hilo(avs[i], hi, lo);
            *(uint2*)&As[nb][r * AST + q * 4]      = hi;
            *(uint2*)&As[nb][r * AST + 16 + q * 4] = lo;
        }
#pragma unroll
        for (int i = 0; i < B_F4; i++) {
            int idx = i * 256 + tid;
            int r, q;
            if (BN == 128) { r = idx >> 5; q = idx & 31; }
            else           { r = idx >> 4; q = idx & 15; }
            uint2 hi, lo; cvt_hilo(bvs[i], hi, lo);
            *(uint2*)&Bs[nb][r * BST + q * 4]      = hi;
            *(uint2*)&Bs[nb][r * BST + BN + q * 4] = lo;
        }
        __syncthreads();
    }

    // ---- epilogue ----
    const int row0 = rowBase + warpM + (lane >> 2);
    const int col0 = colBase + warpN + (lane & 3) * 2;
#pragma unroll
    for (int mi = 0; mi < 4; mi++) {
#pragma unroll
        for (int ni = 0; ni < NF; ni++) {
#pragma unroll
            for (int half = 0; half < 2; half++) {
                int row = row0 + mi * 16 + half * 8;
                int col = col0 + ni * 8;
                float d0 = acc[mi][ni][half * 2 + 0];
                float d1 = acc[mi][ni][half * 2 + 1];
                float* co = Cm + (size_t)row * ldc + col;
                if (EPI == EPI_NONE) {
                    co[0] = d0; co[1] = d1;
                } else if (EPI == EPI_TANH) {
                    co[0] = tanhf(d0); co[1] = tanhf(d1);
                } else if (EPI == EPI_WEXP) {
                    co[0] = expf(-expf(bias[col] + d0));
                    co[1] = expf(-expf(bias[col + 1] + d1));
                } else { // EPI_MIX: out = x + xx*(tmaa + acc)
                    float2 xv  = *(const float2*)(px  + (size_t)row * ldc + col);
                    float2 xxv = *(const float2*)(pxx + (size_t)row * ldc + col);
                    co[0] = fmaf(xxv.x, bias[col] + d0, xv.x);
                    co[1] = fmaf(xxv.y, bias[col + 1] + d1, xv.y);
                }
            }
        }
    }
}

// ---------------- elementwise: token shift + maa_x mix ----------------
__global__ void __launch_bounds__(256) k_shift(const float4* __restrict__ x,
                                               const float4* __restrict__ tmx,
                                               float4* __restrict__ oxx,
                                               float4* __restrict__ oxxx)
{
    int i = blockIdx.x * 256 + threadIdx.x;
    int c4 = i & (C4 - 1);
    int n  = i >> 8;
    int t  = n & (Tc - 1);
    float4 xv = x[i];
    float4 xp = make_float4(0.f, 0.f, 0.f, 0.f);
    if (t != 0) xp = x[i - C4];
    float4 d;
    d.x = xp.x - xv.x; d.y = xp.y - xv.y; d.z = xp.z - xv.z; d.w = xp.w - xv.w;
    float4 tm = tmx[c4];
    float4 o;
    o.x = fmaf(d.x, tm.x, xv.x); o.y = fmaf(d.y, tm.y, xv.y);
    o.z = fmaf(d.z, tm.z, xv.z); o.w = fmaf(d.w, tm.w, xv.w);
    oxx[i]  = d;
    oxxx[i] = o;
}

// ---------------- WKV6 recurrence ----------------
#define WKV_CT 64
__global__ void __launch_bounds__(32) k_wkv(const float* __restrict__ u_faaaa,
                                            const float* __restrict__ r,
                                            const float* __restrict__ k,
                                            const float* __restrict__ v,
                                            const float* __restrict__ w,
                                            float* __restrict__ y)
{
    const int head_id = blockIdx.x;
    const int b = head_id >> 6;
    const int h = head_id & 63;
    const int lane = threadIdx.x;
    const int ih = lane >> 4;
    const int j  = lane & 15;
    const int base = (b * Tc) * (Hc * HSc) + h * HSc;

    float S[8];
#pragma unroll
    for (int q = 0; q < 8; q++) S[q] = 0.f;
    float u[8];
#pragma unroll
    for (int q = 0; q < 8; q++) u[q] = u_faaaa[h * HSc + ih * 8 + q];

    __shared__ float4 rkw[WKV_CT][HSc];
    __shared__ float  vsh[WKV_CT][HSc];

    for (int t0 = 0; t0 < Tc; t0 += WKV_CT) {
#pragma unroll 4
        for (int idx = lane; idx < WKV_CT * HSc; idx += 32) {
            int tt = idx >> 4;
            int i  = idx & 15;
            int off = base + (t0 + tt) * (Hc * HSc) + i;
            rkw[tt][i] = make_float4(r[off], k[off], w[off], 0.f);
            vsh[tt][i] = v[off];
        }
        __syncwarp();
        for (int tt = 0; tt < WKV_CT; ++tt) {
            float vj  = vsh[tt][j];
            float acc = 0.f;
#pragma unroll
            for (int q = 0; q < 8; q++) {
                float4 e = rkw[tt][ih * 8 + q];
                float kv = e.y * vj;
                acc  = fmaf(e.x, fmaf(u[q], kv, S[q]), acc);
                S[q] = fmaf(e.z, S[q], kv);
            }
            acc += __shfl_xor_sync(0xffffffffu, acc, 16);
            if (ih == 0) y[base + (t0 + tt) * (Hc * HSc) + j] = acc;
        }
        __syncwarp();
    }
}

// ---------------- LayerNorm ----------------
__global__ void __launch_bounds__(256) k_ln(const float* __restrict__ y,
                                            const float* __restrict__ g,
                                            const float* __restrict__ bb,
                                            float* __restrict__ out)
{
    const int n   = blockIdx.x;
    const int tid = threadIdx.x;
    const float4* yr = (const float4*)(y + (size_t)n * Cc);
    float4 vv = yr[tid];
    float s = vv.x + vv.y + vv.z + vv.w;
    float q = vv.x * vv.x + vv.y * vv.y + vv.z * vv.z + vv.w * vv.w;
#pragma unroll
    for (int o = 16; o > 0; o >>= 1) {
        s += __shfl_xor_sync(0xffffffffu, s, o);
        q += __shfl_xor_sync(0xffffffffu, q, o);
    }
    __shared__ float ssh[8], qsh[8];
    if ((tid & 31) == 0) { ssh[tid >> 5] = s; qsh[tid >> 5] = q; }
    __syncthreads();
    float st = 0.f, qt = 0.f;
#pragma unroll
    for (int wix = 0; wix < 8; wix++) { st += ssh[wix]; qt += qsh[wix]; }
    float mean = st * (1.0f / Cc);
    float var  = qt * (1.0f / Cc) - mean * mean;
    float rstd = rsqrtf(var + 1e-5f);
    float4 gg = ((const float4*)g)[tid];
    float4 b4 = ((const float4*)bb)[tid];
    float4 o;
    o.x = (vv.x - mean) * rstd * gg.x + b4.x;
    o.y = (vv.y - mean) * rstd * gg.y + b4.y;
    o.z = (vv.z - mean) * rstd * gg.z + b4.z;
    o.w = (vv.w - mean) * rstd * gg.w + b4.w;
    ((float4*)(out + (size_t)n * Cc))[tid] = o;
}

// ---------------- launcher ----------------
extern "C" void kernel_launch(void* const* d_in, const int* in_sizes, int n_in,
                              void* d_out, int out_size)
{
    (void)in_sizes; (void)n_in; (void)out_size;
    const float* x     = (const float*)d_in[0];
    const float* tmx   = (const float*)d_in[1];
    const float* tmw   = (const float*)d_in[2];
    const float* tmk   = (const float*)d_in[3];
    const float* tmv   = (const float*)d_in[4];
    const float* tmr   = (const float*)d_in[5];
    const float* w1    = (const float*)d_in[6];   // [C,128]
    const float* w2    = (const float*)d_in[7];   // [4,32,C]
    const float* tdec  = (const float*)d_in[8];   // [C]
    const float* dw1   = (const float*)d_in[9];   // [C,64]
    const float* dw2   = (const float*)d_in[10];  // [64,C]
    const float* faaaa = (const float*)d_in[11];  // [H,HS]
    const float* Wr    = (const float*)d_in[12];
    const float* Wk    = (const float*)d_in[13];
    const float* Wv    = (const float*)d_in[14];
    const float* Wo    = (const float*)d_in[15];
    const float* lng   = (const float*)d_in[16];
    const float* lnb   = (const float*)d_in[17];
    float* out = (float*)d_out;

    static float *p_xx = nullptr, *p_xxx, *p_h, *p_r, *p_k, *p_v, *p_we,
                 *p_xw, *p_xk, *p_xv, *p_xr, *p_t1;
    if (!p_xx) {
        cudaGetSymbolAddress((void**)&p_xx,  g_xx);
        cudaGetSymbolAddress((void**)&p_xxx, g_xxx);
        cudaGetSymbolAddress((void**)&p_h,   g_h);
        cudaGetSymbolAddress((void**)&p_r,   g_r);
        cudaGetSymbolAddress((void**)&p_k,   g_k);
        cudaGetSymbolAddress((void**)&p_v,   g_v);
        cudaGetSymbolAddress((void**)&p_we,  g_we);
        cudaGetSymbolAddress((void**)&p_xw,  g_xw);
        cudaGetSymbolAddress((void**)&p_xk,  g_xk);
        cudaGetSymbolAddress((void**)&p_xv,  g_xv);
        cudaGetSymbolAddress((void**)&p_xr,  g_xr);
        cudaGetSymbolAddress((void**)&p_t1,  g_t1);
    }
    float* p_y  = p_xx;    // y overwrites xx
    float* p_yn = p_xxx;   // ln(y) overwrites xxx

    // 1) token shift + maa_x mix
    k_shift<<<NTOK, 256>>>((const float4*)x, (const float4*)tmx,
                           (float4*)p_xx, (float4*)p_xxx);

    // 2) h = tanh(xxx @ w1)   [8192,1024]x[1024,128]
    mgemm<128, EPI_TANH><<<dim3(NTOK / 128, 1), 256>>>(
        p_xxx, w1, p_h, Cc, Cc, DM4, DM4, nullptr, nullptr, nullptr);

    // 3+4 fused) x{w,k,v,r} = x + xx*(tm + h_f @ w2[f])  [8192,32]x[32,1024]
    {
        const float* tms[4]  = { tmw, tmk, tmv, tmr };
        float*       outs[4] = { p_xw, p_xk, p_xv, p_xr };
        for (int f = 0; f < 4; ++f)
            mgemm<128, EPI_MIX><<<dim3(NTOK / 128, Cc / 128), 256>>>(
                p_h + f * 32, w2 + (size_t)f * 32 * Cc, outs[f],
                32, DM4, Cc, Cc, tms[f], x, p_xx);
    }

    // 5) t1 = tanh(xw @ dw1)  [8192,1024]x[1024,64]
    mgemm<64, EPI_TANH><<<dim3(NTOK / 128, 1), 256>>>(
        p_xw, dw1, p_t1, Cc, Cc, DDEC, DDEC, nullptr, nullptr, nullptr);

    // 6) we = exp(-exp(tdec + t1 @ dw2))  [8192,64]x[64,1024]
    mgemm<128, EPI_WEXP><<<dim3(NTOK / 128, Cc / 128), 256>>>(
        p_t1, dw2, p_we, DDEC, DDEC, Cc, Cc, tdec, nullptr, nullptr);

    // 7) r/k/v projections  [8192,1024]x[1024,1024]
    mgemm<128, EPI_NONE><<<dim3(NTOK / 128, Cc / 128), 256>>>(
        p_xr, Wr, p_r, Cc, Cc, Cc, Cc, nullptr, nullptr, nullptr);
    mgemm<128, EPI_NONE><<<dim3(NTOK / 128, Cc / 128), 256>>>(
        p_xk, Wk, p_k, Cc, Cc, Cc, Cc, nullptr, nullptr, nullptr);
    mgemm<128, EPI_NONE><<<dim3(NTOK / 128, Cc / 128), 256>>>(
        p_xv, Wv, p_v, Cc, Cc, Cc, Cc, nullptr, nullptr, nullptr);

    // 8) WKV6
    k_wkv<<<Bc * Hc, 32>>>(faaaa, p_r, p_k, p_v, p_we, p_y);

    // 9) LayerNorm
    k_ln<<<NTOK, 256>>>(p_y, lng, lnb, p_yn);

    // 10) out = ybar @ W_o
    mgemm<128, EPI_NONE><<<dim3(NTOK / 128, Cc / 128), 256>>>(
        p_yn, Wo, out, Cc, Cc, Cc, Cc, nullptr, nullptr, nullptr);
}